// round 8
// baseline (speedup 1.0000x reference)
#include <cuda_runtime.h>
#include <math.h>

#define Bdim 128
#define Ndim 32
#define Tdim 50
#define Hdim 128
#define HOPS 8
#define NT (Ndim * Tdim)        // 1600
#define THREADS 512
#define NWARPS (THREADS / 32)   // 16
#define PIPE 4                  // rows in flight per warp
#define SCST 1604               // padded score row stride (1604 % 32 == 4; float4-aligned)

// smem layout (floats): node[Tdim*Hdim] | scores[HOPS*SCST] | stage[NWARPS*Hdim]
#define SMEM_FLOATS (Tdim * Hdim + HOPS * SCST + NWARPS * Hdim)

typedef unsigned long long ull;

#define MUL2(d, a, b) \
    asm("mul.rn.f32x2 %0, %1, %2;" : "=l"(d) : "l"(a), "l"(b))
#define FMA2(d, a, b, c) \
    asm("fma.rn.f32x2 %0, %1, %2, %3;" : "=l"(d) : "l"(a), "l"(b), "l"(c))

__device__ __forceinline__ ull pack2(float lo, float hi) {
    ull r; asm("mov.b64 %0, {%1, %2};" : "=l"(r) : "f"(lo), "f"(hi)); return r;
}
__device__ __forceinline__ float2 unpack2(ull v) {
    float lo, hi; asm("mov.b64 {%0, %1}, %2;" : "=f"(lo), "=f"(hi) : "l"(v));
    return make_float2(lo, hi);
}

__global__ __launch_bounds__(THREADS, 1)
void guided_attn_kernel(const float* __restrict__ node,
                        const float* __restrict__ neigh,
                        const int* __restrict__ nn,
                        const float* __restrict__ W,
                        const float* __restrict__ bias,
                        float* __restrict__ out)
{
    const int b    = blockIdx.x;
    const int tid  = threadIdx.x;
    const int wid  = tid >> 5;
    const int lane = tid & 31;
    const int m    = lane & 3;   // h-quarter
    const int a    = lane >> 2;  // hop (0..7)

    extern __shared__ float smem[];
    float* s_node   = smem;                       // 6400
    float* s_scores = s_node + Tdim * Hdim;       // 8*1604
    float* s_stage  = s_scores + HOPS * SCST;     // 16*128

    float* outBW = out;                                      // B*NT
    float* outBA = out + (size_t)Bdim * NT;                  // B*HOPS*NT
    float* outNR = outBA + (size_t)Bdim * HOPS * NT;         // B*NT*H

    // ---- load node[b] into smem ----
    const float4* node_b = (const float4*)(node + (size_t)b * Tdim * Hdim);
    float4* s_node4 = (float4*)s_node;
    #pragma unroll 4
    for (int i = tid; i < (Tdim * Hdim) / 4; i += THREADS) s_node4[i] = node_b[i];

    // ---- per-lane W slice in registers (packed f32x2): hop a, h = m*4 + i*16 .. +3 ----
    ull wpak[8][2];
    #pragma unroll
    for (int i = 0; i < 8; i++) {
        const float4 w = *(const float4*)(W + a * Hdim + m * 4 + i * 16);
        wpak[i][0] = pack2(w.x, w.y);
        wpak[i][1] = pack2(w.z, w.w);
    }
    const float my_bias   = bias[a];
    const float inv_scale = 1.0f / sqrtf((float)nn[0]);

    __syncthreads();

    // ---- main stream: copy neigh -> neigh_r, compute 8 hop scores per row ----
    // 100 rows per warp, 4-deep software pipeline (100 % 4 == 0, no tail).
    const float4* neigh_b = (const float4*)(neigh + (size_t)b * NT * Hdim);
    float4*       nr_b    = (float4*)(outNR + (size_t)b * NT * Hdim);
    float4*       stage4  = (float4*)(s_stage + wid * Hdim);
    const ulonglong2* stage2 = (const ulonglong2*)stage4;

    float4 buf[PIPE];
    #pragma unroll
    for (int j = 0; j < PIPE; j++)
        buf[j] = __ldcs(&neigh_b[(wid + j * NWARPS) * 32 + lane]);

    for (int base = wid; base < NT; base += PIPE * NWARPS) {
        #pragma unroll
        for (int j = 0; j < PIPE; j++) {
            const int nt  = base + j * NWARPS;
            const int pre = nt + PIPE * NWARPS;
            const float4 cur = buf[j];
            if (pre < NT) buf[j] = __ldcs(&neigh_b[pre * 32 + lane]);

            __stcs(&nr_b[nt * 32 + lane], cur);         // the neigh_r copy
            stage4[lane] = cur;
            __syncwarp();

            const int t = nt % Tdim;
            const ulonglong2* s_nd = (const ulonglong2*)(s_node + t * Hdim);

            ull acc0 = 0ull, acc1 = 0ull;               // packed (0.f, 0.f)
            #pragma unroll
            for (int i = 0; i < 8; i++) {
                const ulonglong2 nv = stage2[m + i * 4]; // 4 distinct addrs + broadcast
                const ulonglong2 dv = s_nd[m + i * 4];
                ull p0, p1;
                MUL2(p0, nv.x, dv.x);
                FMA2(acc0, p0, wpak[i][0], acc0);
                MUL2(p1, nv.y, dv.y);
                FMA2(acc1, p1, wpak[i][1], acc1);
            }
            const float2 a0 = unpack2(acc0);
            const float2 a1 = unpack2(acc1);
            float acc = (a0.x + a0.y) + (a1.x + a1.y);

            // reduce over the 4 quarter-lanes of this hop
            acc += __shfl_xor_sync(0xffffffffu, acc, 1);
            acc += __shfl_xor_sync(0xffffffffu, acc, 2);
            if (m == 0)
                s_scores[a * SCST + nt] = (acc + my_bias) * inv_scale;
            // shfl is the warp convergence point: stage reads are done
        }
    }

    __syncthreads();

    // ---- softmax: warp w owns hop w ----
    if (wid < HOPS) {
        float* row = s_scores + wid * SCST;
        float mx = -3.0e38f;
        for (int i = lane; i < NT; i += 32) mx = fmaxf(mx, row[i]);
        #pragma unroll
        for (int o = 16; o; o >>= 1) mx = fmaxf(mx, __shfl_xor_sync(0xffffffffu, mx, o));

        float s = 0.f;
        for (int i = lane; i < NT; i += 32) {
            const float e = __expf(row[i] - mx);
            row[i] = e;
            s += e;
        }
        #pragma unroll
        for (int o = 16; o; o >>= 1) s += __shfl_xor_sync(0xffffffffu, s, o);
        const float inv = 1.0f / s;

        float* ba = outBA + ((size_t)b * HOPS + wid) * NT;
        for (int i = lane; i < NT; i += 32) {
            const float v = row[i] * inv;
            row[i] = v;
            __stcs(&ba[i], v);                          // streaming: no reuse
        }
    }
    __syncthreads();

    // ---- BW = sum over hops (vectorized: NT/4 = 400 float4 lanes) ----
    float4* bw4 = (float4*)(outBW + (size_t)b * NT);
    for (int i = tid; i < NT / 4; i += THREADS) {
        float4 s = make_float4(0.f, 0.f, 0.f, 0.f);
        #pragma unroll
        for (int aa = 0; aa < HOPS; aa++) {
            const float4 v = *(const float4*)(s_scores + aa * SCST + i * 4);
            s.x += v.x; s.y += v.y; s.z += v.z; s.w += v.w;
        }
        __stcs(&bw4[i], s);
    }
}

extern "C" void kernel_launch(void* const* d_in, const int* in_sizes, int n_in,
                              void* d_out, int out_size)
{
    const float* node  = (const float*)d_in[0];
    const float* neigh = (const float*)d_in[1];
    const int*   nn    = (const int*)d_in[2];
    const float* W     = (const float*)d_in[3];
    const float* bias  = (const float*)d_in[4];
    float*       out   = (float*)d_out;

    const size_t smem_bytes = (size_t)SMEM_FLOATS * sizeof(float);  // ~85 KB
    cudaFuncSetAttribute(guided_attn_kernel,
                         cudaFuncAttributeMaxDynamicSharedMemorySize,
                         (int)smem_bytes);

    guided_attn_kernel<<<Bdim, THREADS, smem_bytes>>>(node, neigh, nn, W, bias, out);
}

// round 11
// speedup vs baseline: 1.3307x; 1.3307x over previous
#include <cuda_runtime.h>
#include <math.h>

#define Bdim 128
#define Ndim 32
#define Tdim 50
#define Hdim 128
#define HOPS 8
#define NT (Ndim * Tdim)        // 1600
#define THREADS 512
#define NWARPS (THREADS / 32)   // 16
#define PIPE 4                  // rows in flight per warp
#define SCST 1604               // padded score row stride (1604 % 32 == 4; float4-aligned)

// smem layout (floats): node[Tdim*Hdim] | scores[HOPS*SCST] | stage[NWARPS*Hdim]
#define SMEM_FLOATS (Tdim * Hdim + HOPS * SCST + NWARPS * Hdim)

typedef unsigned long long ull;

#define MUL2(d, a, b) \
    asm("mul.rn.f32x2 %0, %1, %2;" : "=l"(d) : "l"(a), "l"(b))
#define FMA2(d, a, b, c) \
    asm("fma.rn.f32x2 %0, %1, %2, %3;" : "=l"(d) : "l"(a), "l"(b), "l"(c))

__device__ __forceinline__ float2 unpack2(ull v) {
    float lo, hi; asm("mov.b64 {%0, %1}, %2;" : "=f"(lo), "=f"(hi) : "l"(v));
    return make_float2(lo, hi);
}

__global__ __launch_bounds__(THREADS, 1)
void guided_attn_kernel(const float* __restrict__ node,
                        const float* __restrict__ neigh,
                        const int* __restrict__ nn,
                        const float* __restrict__ W,
                        const float* __restrict__ bias,
                        float* __restrict__ out)
{
    const int b    = blockIdx.x;
    const int tid  = threadIdx.x;
    const int wid  = tid >> 5;
    const int lane = tid & 31;
    const int p    = lane & 3;   // hop-pair: hops 2p, 2p+1
    const int o    = lane >> 2;  // h-octant: h = o*16 .. o*16+15

    extern __shared__ float smem[];
    float* s_node   = smem;                       // 6400
    float* s_scores = s_node + Tdim * Hdim;       // 8*1604
    float* s_stage  = s_scores + HOPS * SCST;     // 16*128

    float* outBW = out;                                      // B*NT
    float* outBA = out + (size_t)Bdim * NT;                  // B*HOPS*NT
    float* outNR = outBA + (size_t)Bdim * HOPS * NT;         // B*NT*H

    // ---- load node[b] into smem ----
    const float4* node_b = (const float4*)(node + (size_t)b * Tdim * Hdim);
    float4* s_node4 = (float4*)s_node;
    #pragma unroll 4
    for (int i = tid; i < (Tdim * Hdim) / 4; i += THREADS) s_node4[i] = node_b[i];

    // ---- per-lane W slices: hops 2p and 2p+1, h = o*16 .. o*16+15, as packed pairs ----
    // Adjacent-float pairs == plain 64-bit loads (8B-aligned).
    ull wA[8], wB[8];
    {
        const ull* wra = (const ull*)(W + (2 * p)     * Hdim + o * 16);
        const ull* wrb = (const ull*)(W + (2 * p + 1) * Hdim + o * 16);
        #pragma unroll
        for (int j = 0; j < 8; j++) { wA[j] = wra[j]; wB[j] = wrb[j]; }
    }
    const float inv_scale = 1.0f / sqrtf((float)nn[0]);
    const float bs0 = bias[2 * p]     * inv_scale;   // (s + b)*inv == s*inv + b*inv
    const float bs1 = bias[2 * p + 1] * inv_scale;

    __syncthreads();

    // ---- main stream: copy neigh -> neigh_r, compute 8 hop scores per row ----
    // 100 rows per warp, 4-deep software pipeline (100 % 4 == 0, no tail).
    const float4* neigh_b = (const float4*)(neigh + (size_t)b * NT * Hdim);
    float4*       nr_b    = (float4*)(outNR + (size_t)b * NT * Hdim);
    float4*       stage4  = (float4*)(s_stage + wid * Hdim);
    const ulonglong2* stage2 = (const ulonglong2*)stage4;

    float4 buf[PIPE];
    #pragma unroll
    for (int j = 0; j < PIPE; j++)
        buf[j] = __ldcs(&neigh_b[(wid + j * NWARPS) * 32 + lane]);

    for (int base = wid; base < NT; base += PIPE * NWARPS) {
        #pragma unroll
        for (int j = 0; j < PIPE; j++) {
            const int nt  = base + j * NWARPS;
            const int pre = nt + PIPE * NWARPS;
            const float4 cur = buf[j];
            if (pre < NT) buf[j] = __ldcs(&neigh_b[pre * 32 + lane]);

            __stcs(&nr_b[nt * 32 + lane], cur);         // the neigh_r copy
            stage4[lane] = cur;                         // lane owns h-chunk `lane`
            __syncwarp();

            const int t = nt % Tdim;
            const ulonglong2* s_nd2 = (const ulonglong2*)(s_node + t * Hdim);

            // dot over this lane's 16 h-values for hops 2p (acc0) and 2p+1 (acc1)
            ull acc0 = 0ull, acc1 = 0ull;
            #pragma unroll
            for (int k = 0; k < 4; k++) {
                const int c = o * 4 + k;                // 16B chunk index (8 distinct, 4-way bcast)
                const ulonglong2 sv = stage2[c];
                const ulonglong2 dv = s_nd2[c];
                ull q0, q1;
                MUL2(q0, sv.x, dv.x);
                MUL2(q1, sv.y, dv.y);
                FMA2(acc0, q0, wA[2 * k],     acc0);
                FMA2(acc0, q1, wA[2 * k + 1], acc0);
                FMA2(acc1, q0, wB[2 * k],     acc1);
                FMA2(acc1, q1, wB[2 * k + 1], acc1);
            }
            const float2 a0 = unpack2(acc0);
            const float2 a1 = unpack2(acc1);
            float s0 = a0.x + a0.y;
            float s1 = a1.x + a1.y;

            // reduce over the 8 octants (lane bits 2..4)
            #pragma unroll
            for (int off = 4; off <= 16; off <<= 1) {
                s0 += __shfl_xor_sync(0xffffffffu, s0, off);
                s1 += __shfl_xor_sync(0xffffffffu, s1, off);
            }
            if (o == 0) {
                s_scores[(2 * p)     * SCST + nt] = fmaf(s0, inv_scale, bs0);
                s_scores[(2 * p + 1) * SCST + nt] = fmaf(s1, inv_scale, bs1);
            }
            // shfl is the warp convergence point: stage reads are done
        }
    }

    __syncthreads();

    // ---- softmax: warp w owns hop w ----
    if (wid < HOPS) {
        float* row = s_scores + wid * SCST;
        float mx = -3.0e38f;
        for (int i = lane; i < NT; i += 32) mx = fmaxf(mx, row[i]);
        #pragma unroll
        for (int off = 16; off; off >>= 1) mx = fmaxf(mx, __shfl_xor_sync(0xffffffffu, mx, off));

        float s = 0.f;
        for (int i = lane; i < NT; i += 32) {
            const float e = __expf(row[i] - mx);
            row[i] = e;
            s += e;
        }
        #pragma unroll
        for (int off = 16; off; off >>= 1) s += __shfl_xor_sync(0xffffffffu, s, off);
        const float inv = 1.0f / s;

        float* ba = outBA + ((size_t)b * HOPS + wid) * NT;
        for (int i = lane; i < NT; i += 32) {
            const float v = row[i] * inv;
            row[i] = v;
            __stcs(&ba[i], v);                          // streaming: no reuse
        }
    }
    __syncthreads();

    // ---- BW = sum over hops (vectorized: NT/4 = 400 float4 lanes) ----
    float4* bw4 = (float4*)(outBW + (size_t)b * NT);
    for (int i = tid; i < NT / 4; i += THREADS) {
        float4 s = make_float4(0.f, 0.f, 0.f, 0.f);
        #pragma unroll
        for (int aa = 0; aa < HOPS; aa++) {
            const float4 v = *(const float4*)(s_scores + aa * SCST + i * 4);
            s.x += v.x; s.y += v.y; s.z += v.z; s.w += v.w;
        }
        __stcs(&bw4[i], s);
    }
}

extern "C" void kernel_launch(void* const* d_in, const int* in_sizes, int n_in,
                              void* d_out, int out_size)
{
    const float* node  = (const float*)d_in[0];
    const float* neigh = (const float*)d_in[1];
    const int*   nn    = (const int*)d_in[2];
    const float* W     = (const float*)d_in[3];
    const float* bias  = (const float*)d_in[4];
    float*       out   = (float*)d_out;

    const size_t smem_bytes = (size_t)SMEM_FLOATS * sizeof(float);  // ~85 KB
    cudaFuncSetAttribute(guided_attn_kernel,
                         cudaFuncAttributeMaxDynamicSharedMemorySize,
                         (int)smem_bytes);

    guided_attn_kernel<<<Bdim, THREADS, smem_bytes>>>(node, neigh, nn, W, bias, out);
}